// round 6
// baseline (speedup 1.0000x reference)
#include <cuda_runtime.h>
#include <cuda_bf16.h>

// ---------------------------------------------------------------------------
// MATLABStyleEnhancement: dehaze + guided filter + percentile stretch
// B=8, C=3, H=W=512
// ---------------------------------------------------------------------------

#define Bn 8
#define Hh 512
#define Ww 512
#define NP (Hh * Ww)            // 262144 = 2^18
#define NBC (Bn * 3)            // 24
#define PADW 616                // Ww + 2*50 + pad
#define YSEG 64
#define H1BINS 16384
#define H2BINS 65536

// ------------------------- device scratch ----------------------------------
__device__ float g_gray[Bn * NP];
__device__ float g_tg[Bn * NP];
__device__ float g_h0[Bn * NP];
__device__ float g_h1[Bn * NP];
__device__ float g_h2[Bn * NP];
__device__ float g_h3[Bn * NP];
__device__ float g_a[Bn * NP];
__device__ float g_b[Bn * NP];
__device__ float g_J[NBC * NP];
__device__ unsigned g_hist1[NBC * H1BINS];
__device__ unsigned g_hist2[NBC * 2 * H2BINS];
__device__ int g_selPrefix[NBC * 2];
__device__ unsigned g_selRank[NBC * 2];
__device__ float g_plow[NBC];
__device__ float g_phigh[NBC];
__device__ float g_pscale[NBC];

__device__ __forceinline__ int reflect(int i, int n) {
    if (i < 0) i = -i;
    if (i >= n) i = 2 * n - 2 - i;
    return i;
}

__device__ __forceinline__ int get_r(const int* rp) {
    int r = rp ? *rp : 15;
    return max(1, min(r, 50));
}

// ------------------- 0. zero histograms ------------------------------------
__global__ void zero_kernel() {
    const int tot1 = NBC * H1BINS;
    const int tot2 = NBC * 2 * H2BINS;
    for (int i = blockIdx.x * blockDim.x + threadIdx.x; i < tot1 + tot2;
         i += gridDim.x * blockDim.x) {
        if (i < tot1) g_hist1[i] = 0u;
        else          g_hist2[i - tot1] = 0u;
    }
}

// ------------------- 1. gray + gradient-constrained transmission -----------
__global__ void k1_kernel(const float* __restrict__ img,
                          const float* __restrict__ omega,
                          const float* __restrict__ atm) {
    int i = blockIdx.x * blockDim.x + threadIdx.x;
    if (i >= Bn * NP) return;
    int b = i >> 18;
    int p = i & (NP - 1);
    int y = p >> 9;
    int x = p & 511;

    float ra = 1.0f / (atm[b * 3 + 0] + 1e-8f);
    float rg = 1.0f / (atm[b * 3 + 1] + 1e-8f);
    float rb = 1.0f / (atm[b * 3 + 2] + 1e-8f);
    float om = omega[b];
    const float* ib = img + b * 3 * NP;

    float c0 = ib[p], c1 = ib[NP + p], c2 = ib[2 * NP + p];
    float t_cur = 1.0f - om * fminf(fminf(c0 * ra, c1 * rg), c2 * rb);
    float gray = c0 * 0.299f + c1 * 0.587f + c2 * 0.114f;

    float t_up;
    if (y > 0) {
        int pu = p - Ww;
        float u0 = ib[pu], u1 = ib[NP + pu], u2 = ib[2 * NP + pu];
        t_up = 1.0f - om * fminf(fminf(u0 * ra, u1 * rg), u2 * rb);
    } else {
        t_up = t_cur;   // row 0: "up" row is row 0 itself
    }

    float tx;
    if (x == 0) {
        tx = t_up;      // tx[yy][0] = t0[yy][0]
    } else {
        int pl = (y > 0 ? p - Ww : p) - 1;
        float l0 = ib[pl], l1 = ib[NP + pl], l2 = ib[2 * NP + pl];
        float t_left = 1.0f - om * fminf(fminf(l0 * ra, l1 * rg), l2 * rb);
        tx = t_left * expf(-fabsf(t_up - t_left));
    }
    float tg = (y > 0) ? tx * expf(-fabsf(t_cur - t_up)) : tx;

    g_gray[i] = gray;
    g_tg[i] = tg;
}

// ------------------- 2. horizontal box sums (stage 1, 4 quantities) --------
__global__ void h1_kernel(const int* rp) {
    __shared__ float sg[PADW], st[PADW], sgt[PADW], sgg[PADW];
    int r = get_r(rp);
    int k2r = 2 * r;
    int base = blockIdx.x * Ww;        // (b*512+y)*512
    int plen = Ww + k2r;

    for (int ii = threadIdx.x; ii < plen; ii += 64) {
        int x = reflect(ii - r, Ww);
        float g = g_gray[base + x];
        float t = g_tg[base + x];
        sg[ii] = g; st[ii] = t; sgt[ii] = g * t; sgg[ii] = g * g;
    }
    __syncthreads();

    int x0 = threadIdx.x * 8;
    float s0 = 0.f, s1 = 0.f, s2 = 0.f, s3 = 0.f;
    for (int j = 0; j <= k2r; j++) {
        s0 += sg[x0 + j]; s1 += st[x0 + j]; s2 += sgt[x0 + j]; s3 += sgg[x0 + j];
    }
    for (int u = 0; u < 8; u++) {
        int x = x0 + u;
        g_h0[base + x] = s0; g_h1[base + x] = s1;
        g_h2[base + x] = s2; g_h3[base + x] = s3;
        if (u < 7) {
            int ia = x + k2r + 1;
            s0 += sg[ia] - sg[x]; s1 += st[ia] - st[x];
            s2 += sgt[ia] - sgt[x]; s3 += sgg[ia] - sgg[x];
        }
    }
}

// ------------------- 3. vertical box sums (stage 1) -> a,b ------------------
__global__ void v1_kernel(const int* rp) {
    int r = get_r(rp);
    int b = blockIdx.z;
    int x = blockIdx.x * blockDim.x + threadIdx.x;
    int y0 = blockIdx.y * YSEG;
    int pb = b * NP;

    float s0 = 0.f, s1 = 0.f, s2 = 0.f, s3 = 0.f;
    for (int j = -r; j <= r; j++) {
        int off = pb + reflect(y0 + j, Hh) * Ww + x;
        s0 += g_h0[off]; s1 += g_h1[off]; s2 += g_h2[off]; s3 += g_h3[off];
    }
    float k = (float)(2 * r + 1);
    float inv = 1.0f / (k * k);

    for (int y = y0; y < y0 + YSEG; y++) {
        float mI = s0 * inv, mp = s1 * inv, mIp = s2 * inv, mGG = s3 * inv;
        float a = (mIp - mI * mp) / ((mGG - mI * mI) + 0.5f);
        float bb = mp - a * mI;
        int o = pb + y * Ww + x;
        g_a[o] = a; g_b[o] = bb;
        int ya = pb + reflect(y + r + 1, Hh) * Ww + x;
        int yo = pb + reflect(y - r, Hh) * Ww + x;
        s0 += g_h0[ya] - g_h0[yo]; s1 += g_h1[ya] - g_h1[yo];
        s2 += g_h2[ya] - g_h2[yo]; s3 += g_h3[ya] - g_h3[yo];
    }
}

// ------------------- 4. horizontal box sums (stage 2, a & b) ----------------
__global__ void h2_kernel(const int* rp) {
    __shared__ float sa[PADW], sb[PADW];
    int r = get_r(rp);
    int k2r = 2 * r;
    int base = blockIdx.x * Ww;
    int plen = Ww + k2r;

    for (int ii = threadIdx.x; ii < plen; ii += 64) {
        int x = reflect(ii - r, Ww);
        sa[ii] = g_a[base + x];
        sb[ii] = g_b[base + x];
    }
    __syncthreads();

    int x0 = threadIdx.x * 8;
    float s0 = 0.f, s1 = 0.f;
    for (int j = 0; j <= k2r; j++) { s0 += sa[x0 + j]; s1 += sb[x0 + j]; }
    for (int u = 0; u < 8; u++) {
        int x = x0 + u;
        g_h0[base + x] = s0; g_h1[base + x] = s1;
        if (u < 7) {
            int ia = x + k2r + 1;
            s0 += sa[ia] - sa[x]; s1 += sb[ia] - sb[x];
        }
    }
}

// --------- 5. vertical (stage 2) -> t_final -> J + pass-1 histogram ---------
__global__ void v2_kernel(const float* __restrict__ img,
                          const float* __restrict__ atm,
                          const int* rp) {
    int r = get_r(rp);
    int b = blockIdx.z;
    int x = blockIdx.x * blockDim.x + threadIdx.x;
    int y0 = blockIdx.y * YSEG;
    int pb = b * NP;
    float A0 = atm[b * 3 + 0], A1 = atm[b * 3 + 1], A2 = atm[b * 3 + 2];

    float sA = 0.f, sB = 0.f;
    for (int j = -r; j <= r; j++) {
        int off = pb + reflect(y0 + j, Hh) * Ww + x;
        sA += g_h0[off]; sB += g_h1[off];
    }
    float k = (float)(2 * r + 1);
    float inv = 1.0f / (k * k);
    const float* ib = img + b * 3 * NP;

    for (int y = y0; y < y0 + YSEG; y++) {
        int po = y * Ww + x;
        int o = pb + po;
        float t = fminf(fmaxf(sA * inv * g_gray[o] + sB * inv, 0.1f), 1.0f);
        float it = 1.0f / (t + 1e-8f);
        float J0 = fminf(fmaxf((ib[po] - A0) * it + A0, 0.f), 1.f);
        float J1 = fminf(fmaxf((ib[NP + po] - A1) * it + A1, 0.f), 1.f);
        float J2 = fminf(fmaxf((ib[2 * NP + po] - A2) * it + A2, 0.f), 1.f);
        int jb = b * 3 * NP + po;
        g_J[jb] = J0; g_J[jb + NP] = J1; g_J[jb + 2 * NP] = J2;
        atomicAdd(&g_hist1[(b * 3 + 0) * H1BINS + (__float_as_uint(J0) >> 16)], 1u);
        atomicAdd(&g_hist1[(b * 3 + 1) * H1BINS + (__float_as_uint(J1) >> 16)], 1u);
        atomicAdd(&g_hist1[(b * 3 + 2) * H1BINS + (__float_as_uint(J2) >> 16)], 1u);
        int ya = pb + reflect(y + r + 1, Hh) * Ww + x;
        int yo = pb + reflect(y - r, Hh) * Ww + x;
        sA += g_h0[ya] - g_h0[yo];
        sB += g_h1[ya] - g_h1[yo];
    }
}

// ------------------- 6. select bucket from pass-1 histogram ------------------
__global__ void scan1_kernel(const float* __restrict__ Llow,
                             const float* __restrict__ Lhigh) {
    int bc = blockIdx.x >> 1;
    int sel = blockIdx.x & 1;
    int b = bc / 3;
    float L = sel ? Lhigh[b] : Llow[b];
    int kk = (int)((L / 100.0f) * (float)NP);   // matches (L/100*n).astype(int32)
    kk = max(0, min(kk, NP - 1));
    unsigned ks = (unsigned)kk;
    const unsigned* h = g_hist1 + bc * H1BINS;

    __shared__ unsigned part[257];
    int t = threadIdx.x;                        // 256 threads
    const int CH = H1BINS / 256;                // 64
    unsigned s = 0;
    for (int i = 0; i < CH; i++) s += h[t * CH + i];
    part[t] = s;
    __syncthreads();
    if (t == 0) {
        unsigned run = 0;
        for (int i = 0; i < 256; i++) { unsigned v = part[i]; part[i] = run; run += v; }
        part[256] = run;
    }
    __syncthreads();
    if (ks >= part[t] && ks < part[t + 1]) {
        unsigned cum = part[t];
        for (int i = 0; i < CH; i++) {
            unsigned c = h[t * CH + i];
            if (ks < cum + c) {
                g_selPrefix[blockIdx.x] = t * CH + i;
                g_selRank[blockIdx.x] = ks - cum;
                break;
            }
            cum += c;
        }
    }
}

// ------------------- 7. pass-2 histogram (low 16 bits in bucket) ------------
__global__ void pass2_kernel() {
    __shared__ int sp[NBC * 2];
    if (threadIdx.x < NBC * 2) sp[threadIdx.x] = g_selPrefix[threadIdx.x];
    __syncthreads();
    int i = blockIdx.x * blockDim.x + threadIdx.x;
    if (i >= NBC * NP) return;
    int bc = i >> 18;
    unsigned key = __float_as_uint(g_J[i]);
    int pre = (int)(key >> 16);
    unsigned low = key & 0xFFFFu;
    if (pre == sp[bc * 2])     atomicAdd(&g_hist2[(bc * 2) * H2BINS + low], 1u);
    if (pre == sp[bc * 2 + 1]) atomicAdd(&g_hist2[(bc * 2 + 1) * H2BINS + low], 1u);
}

// ------------------- 8. exact k-th value from pass-2 histogram ---------------
__global__ void scan2_kernel() {
    int idx = blockIdx.x;                       // bc*2 + sel
    const unsigned* h = g_hist2 + idx * H2BINS;
    unsigned ks = g_selRank[idx];

    __shared__ unsigned part[257];
    int t = threadIdx.x;
    const int CH = H2BINS / 256;                // 256
    unsigned s = 0;
    for (int i = 0; i < CH; i++) s += h[t * CH + i];
    part[t] = s;
    __syncthreads();
    if (t == 0) {
        unsigned run = 0;
        for (int i = 0; i < 256; i++) { unsigned v = part[i]; part[i] = run; run += v; }
        part[256] = run;
    }
    __syncthreads();
    if (ks >= part[t] && ks < part[t + 1]) {
        unsigned cum = part[t];
        for (int i = 0; i < CH; i++) {
            unsigned c = h[t * CH + i];
            if (ks < cum + c) {
                unsigned bits = ((unsigned)g_selPrefix[idx] << 16) | (unsigned)(t * CH + i);
                float v = __uint_as_float(bits);
                int bc = idx >> 1;
                if (idx & 1) g_phigh[bc] = v; else g_plow[bc] = v;
                break;
            }
            cum += c;
        }
    }
}

__global__ void pscale_kernel() {
    int bc = threadIdx.x;
    if (bc < NBC) {
        g_pscale[bc] = 1.0f / (g_phigh[bc] - g_plow[bc] + 1e-8f);
    }
}

// ------------------- 9. final normalize -------------------------------------
__global__ void final_kernel(float* __restrict__ out) {
    int i = blockIdx.x * blockDim.x + threadIdx.x;
    if (i >= NBC * NP) return;
    int bc = i >> 18;
    float pl = g_plow[bc], ph = g_phigh[bc], sc = g_pscale[bc];
    float v = g_J[i];
    v = fminf(fmaxf(v, pl), ph);
    float o = (v - pl) * sc;
    out[i] = fminf(fmaxf(o, 0.f), 1.f);
}

// ---------------------------------------------------------------------------
extern "C" void kernel_launch(void* const* d_in, const int* in_sizes, int n_in,
                              void* d_out, int out_size) {
    const float* img   = (const float*)d_in[0];
    const float* omega = (const float*)d_in[1];
    const float* atm   = (const float*)d_in[2];
    const float* Llow  = (const float*)d_in[3];
    const float* Lhigh = (const float*)d_in[4];
    const int*   rp    = (n_in > 5) ? (const int*)d_in[5] : nullptr;
    float* out = (float*)d_out;

    zero_kernel<<<1024, 256>>>();
    k1_kernel<<<(Bn * NP + 255) / 256, 256>>>(img, omega, atm);
    h1_kernel<<<Bn * Hh, 64>>>(rp);
    v1_kernel<<<dim3(Ww / 256, Hh / YSEG, Bn), 256>>>(rp);
    h2_kernel<<<Bn * Hh, 64>>>(rp);
    v2_kernel<<<dim3(Ww / 256, Hh / YSEG, Bn), 256>>>(img, atm, rp);
    scan1_kernel<<<NBC * 2, 256>>>(Llow, Lhigh);
    pass2_kernel<<<(NBC * NP + 255) / 256, 256>>>();
    scan2_kernel<<<NBC * 2, 256>>>();
    pscale_kernel<<<1, 32>>>();
    final_kernel<<<(NBC * NP + 255) / 256, 256>>>(out);
}

// round 7
// speedup vs baseline: 3.8826x; 3.8826x over previous
#include <cuda_runtime.h>
#include <cuda_bf16.h>

// ---------------------------------------------------------------------------
// MATLABStyleEnhancement: dehaze + guided filter + percentile stretch
// B=8, C=3, H=W=512
// ---------------------------------------------------------------------------

#define Bn 8
#define Hh 512
#define Ww 512
#define NP (Hh * Ww)            // 262144 = 2^18
#define NBC (Bn * 3)            // 24
#define YSEG 32
#define H1BINS 16384
#define H2BINS 65536
#define SK(i) ((i) + ((i) >> 3))   // skewed smem index: lane stride 9 -> conflict-free

// ------------------------- device scratch ----------------------------------
__device__ float  g_gray[Bn * NP];
__device__ float  g_tg[Bn * NP];
__device__ float4 g_hA[Bn * NP];         // stage-1 box sums (g, tg, g*tg, g*g)
__device__ float2 g_ab[Bn * NP];         // (a, b)
__device__ float2 g_hB[Bn * NP];         // stage-2 box sums (a, b)
__device__ float  g_J[NBC * NP];
__device__ __align__(16) unsigned g_hist1[NBC * H1BINS];
__device__ __align__(16) unsigned g_hist2[NBC * 2 * H2BINS];
__device__ int g_selPrefix[NBC * 2];
__device__ unsigned g_selRank[NBC * 2];
__device__ float g_plow[NBC];
__device__ float g_phigh[NBC];
__device__ float g_pscale[NBC];

__device__ __forceinline__ int reflect(int i, int n) {
    if (i < 0) i = -i;
    if (i >= n) i = 2 * n - 2 - i;
    return i;
}

__device__ __forceinline__ int get_r(const int* rp) {
    int r = rp ? *rp : 15;
    return max(1, min(r, 50));
}

// warp-aggregated histogram add; key must be < 0x10000; all 32 lanes execute.
__device__ __forceinline__ void whist_add(unsigned* bucket_base, int key, bool participate) {
    int lane = threadIdx.x & 31;
    int mk = participate ? key : (0x10000 + lane);   // unique sentinel for non-participants
    unsigned m = __match_any_sync(0xFFFFFFFFu, mk);
    if (participate && lane == (__ffs(m) - 1))
        atomicAdd(&bucket_base[key], (unsigned)__popc(m));
}

// ------------------- 0. zero histograms ------------------------------------
__global__ void zero_kernel() {
    const int n1 = NBC * H1BINS / 4;           // 98304 uint4
    const int n2 = NBC * 2 * H2BINS / 4;       // 786432 uint4
    int i = blockIdx.x * blockDim.x + threadIdx.x;
    uint4 z = make_uint4(0u, 0u, 0u, 0u);
    if (i < n1) ((uint4*)g_hist1)[i] = z;
    else if (i < n1 + n2) ((uint4*)g_hist2)[i - n1] = z;
}

// ------------------- 1. gray + gradient-constrained transmission -----------
__global__ void k1_kernel(const float* __restrict__ img,
                          const float* __restrict__ omega,
                          const float* __restrict__ atm) {
    int i = blockIdx.x * blockDim.x + threadIdx.x;
    if (i >= Bn * NP) return;
    int b = i >> 18;
    int p = i & (NP - 1);
    int y = p >> 9;
    int x = p & 511;

    float ra = 1.0f / (atm[b * 3 + 0] + 1e-8f);
    float rg = 1.0f / (atm[b * 3 + 1] + 1e-8f);
    float rb = 1.0f / (atm[b * 3 + 2] + 1e-8f);
    float om = omega[b];
    const float* ib = img + b * 3 * NP;

    float c0 = ib[p], c1 = ib[NP + p], c2 = ib[2 * NP + p];
    float t_cur = 1.0f - om * fminf(fminf(c0 * ra, c1 * rg), c2 * rb);
    float gray = c0 * 0.299f + c1 * 0.587f + c2 * 0.114f;

    float t_up;
    if (y > 0) {
        int pu = p - Ww;
        float u0 = ib[pu], u1 = ib[NP + pu], u2 = ib[2 * NP + pu];
        t_up = 1.0f - om * fminf(fminf(u0 * ra, u1 * rg), u2 * rb);
    } else {
        t_up = t_cur;
    }

    float tx;
    if (x == 0) {
        tx = t_up;
    } else {
        int pl = (y > 0 ? p - Ww : p) - 1;
        float l0 = ib[pl], l1 = ib[NP + pl], l2 = ib[2 * NP + pl];
        float t_left = 1.0f - om * fminf(fminf(l0 * ra, l1 * rg), l2 * rb);
        tx = t_left * expf(-fabsf(t_up - t_left));
    }
    float tg = (y > 0) ? tx * expf(-fabsf(t_cur - t_up)) : tx;

    g_gray[i] = gray;
    g_tg[i] = tg;
}

// ------------------- 2. horizontal box sums (stage 1, float4) ---------------
__global__ void h1_kernel(const int* rp) {
    __shared__ float4 s4[704];                  // SK(611)=687 max
    int r = get_r(rp);
    int k2r = 2 * r;
    int base = blockIdx.x * Ww;                 // (b*512+y)*512
    int plen = Ww + k2r;

    for (int ii = threadIdx.x; ii < plen; ii += 64) {
        int x = reflect(ii - r, Ww);
        float g = g_gray[base + x];
        float t = g_tg[base + x];
        s4[SK(ii)] = make_float4(g, t, g * t, g * g);
    }
    __syncthreads();

    int x0 = threadIdx.x * 8;
    float4 s = make_float4(0.f, 0.f, 0.f, 0.f);
    for (int j = 0; j <= k2r; j++) {
        float4 v = s4[SK(x0 + j)];
        s.x += v.x; s.y += v.y; s.z += v.z; s.w += v.w;
    }
    #pragma unroll
    for (int u = 0; u < 8; u++) {
        int x = x0 + u;
        g_hA[base + x] = s;
        if (u < 7) {
            float4 a = s4[SK(x + k2r + 1)];
            float4 d = s4[SK(x)];
            s.x += a.x - d.x; s.y += a.y - d.y;
            s.z += a.z - d.z; s.w += a.w - d.w;
        }
    }
}

// ------------------- 3. vertical box sums (stage 1) -> a,b ------------------
__global__ void v1_kernel(const int* rp) {
    int r = get_r(rp);
    int b = blockIdx.z;
    int x = blockIdx.x * 128 + threadIdx.x;
    int y0 = blockIdx.y * YSEG;
    int pb = b * NP;

    float4 s = make_float4(0.f, 0.f, 0.f, 0.f);
    for (int j = -r; j <= r; j++) {
        float4 h = g_hA[pb + reflect(y0 + j, Hh) * Ww + x];
        s.x += h.x; s.y += h.y; s.z += h.z; s.w += h.w;
    }
    float k = (float)(2 * r + 1);
    float inv = 1.0f / (k * k);

    #pragma unroll 4
    for (int y = y0; y < y0 + YSEG; y++) {
        float mI = s.x * inv, mp = s.y * inv, mIp = s.z * inv, mGG = s.w * inv;
        float a = (mIp - mI * mp) / ((mGG - mI * mI) + 0.5f);
        float bb = mp - a * mI;
        g_ab[pb + y * Ww + x] = make_float2(a, bb);
        float4 ha = g_hA[pb + reflect(y + r + 1, Hh) * Ww + x];
        float4 ho = g_hA[pb + reflect(y - r, Hh) * Ww + x];
        s.x += ha.x - ho.x; s.y += ha.y - ho.y;
        s.z += ha.z - ho.z; s.w += ha.w - ho.w;
    }
}

// ------------------- 4. horizontal box sums (stage 2, float2) ---------------
__global__ void h2_kernel(const int* rp) {
    __shared__ float2 s2[704];
    int r = get_r(rp);
    int k2r = 2 * r;
    int base = blockIdx.x * Ww;
    int plen = Ww + k2r;

    for (int ii = threadIdx.x; ii < plen; ii += 64) {
        int x = reflect(ii - r, Ww);
        s2[SK(ii)] = g_ab[base + x];
    }
    __syncthreads();

    int x0 = threadIdx.x * 8;
    float2 s = make_float2(0.f, 0.f);
    for (int j = 0; j <= k2r; j++) {
        float2 v = s2[SK(x0 + j)];
        s.x += v.x; s.y += v.y;
    }
    #pragma unroll
    for (int u = 0; u < 8; u++) {
        int x = x0 + u;
        g_hB[base + x] = s;
        if (u < 7) {
            float2 a = s2[SK(x + k2r + 1)];
            float2 d = s2[SK(x)];
            s.x += a.x - d.x; s.y += a.y - d.y;
        }
    }
}

// --------- 5. vertical (stage 2) -> t_final -> J + pass-1 histogram ---------
__global__ void v2_kernel(const float* __restrict__ img,
                          const float* __restrict__ atm,
                          const int* rp) {
    int r = get_r(rp);
    int b = blockIdx.z;
    int x = blockIdx.x * 128 + threadIdx.x;
    int y0 = blockIdx.y * YSEG;
    int pb = b * NP;
    float A0 = atm[b * 3 + 0], A1 = atm[b * 3 + 1], A2 = atm[b * 3 + 2];

    float2 s = make_float2(0.f, 0.f);
    for (int j = -r; j <= r; j++) {
        float2 h = g_hB[pb + reflect(y0 + j, Hh) * Ww + x];
        s.x += h.x; s.y += h.y;
    }
    float k = (float)(2 * r + 1);
    float inv = 1.0f / (k * k);
    const float* ib = img + b * 3 * NP;
    unsigned* h1c0 = &g_hist1[(b * 3 + 0) * H1BINS];
    unsigned* h1c1 = &g_hist1[(b * 3 + 1) * H1BINS];
    unsigned* h1c2 = &g_hist1[(b * 3 + 2) * H1BINS];

    for (int y = y0; y < y0 + YSEG; y++) {
        int po = y * Ww + x;
        int o = pb + po;
        float t = fminf(fmaxf(s.x * inv * g_gray[o] + s.y * inv, 0.1f), 1.0f);
        float it = 1.0f / (t + 1e-8f);
        float J0 = fminf(fmaxf((ib[po] - A0) * it + A0, 0.f), 1.f);
        float J1 = fminf(fmaxf((ib[NP + po] - A1) * it + A1, 0.f), 1.f);
        float J2 = fminf(fmaxf((ib[2 * NP + po] - A2) * it + A2, 0.f), 1.f);
        int jb = b * 3 * NP + po;
        g_J[jb] = J0; g_J[jb + NP] = J1; g_J[jb + 2 * NP] = J2;
        whist_add(h1c0, (int)(__float_as_uint(J0) >> 16), true);
        whist_add(h1c1, (int)(__float_as_uint(J1) >> 16), true);
        whist_add(h1c2, (int)(__float_as_uint(J2) >> 16), true);
        float2 ha = g_hB[pb + reflect(y + r + 1, Hh) * Ww + x];
        float2 ho = g_hB[pb + reflect(y - r, Hh) * Ww + x];
        s.x += ha.x - ho.x; s.y += ha.y - ho.y;
    }
}

// ------------------- 6. select bucket from pass-1 histogram ------------------
__global__ void scan1_kernel(const float* __restrict__ Llow,
                             const float* __restrict__ Lhigh) {
    int bc = blockIdx.x >> 1;
    int sel = blockIdx.x & 1;
    int b = bc / 3;
    float L = sel ? Lhigh[b] : Llow[b];
    int kk = (int)((L / 100.0f) * (float)NP);   // matches (L/100*n).astype(int32)
    kk = max(0, min(kk, NP - 1));
    unsigned ks = (unsigned)kk;
    const unsigned* h = g_hist1 + bc * H1BINS;

    __shared__ unsigned part[257];
    int t = threadIdx.x;                        // 256 threads
    const int CH = H1BINS / 256;                // 64
    unsigned s = 0;
    for (int i = 0; i < CH; i++) s += h[t * CH + i];
    part[t] = s;
    __syncthreads();
    if (t == 0) {
        unsigned run = 0;
        for (int i = 0; i < 256; i++) { unsigned v = part[i]; part[i] = run; run += v; }
        part[256] = run;
    }
    __syncthreads();
    if (ks >= part[t] && ks < part[t + 1]) {
        unsigned cum = part[t];
        for (int i = 0; i < CH; i++) {
            unsigned c = h[t * CH + i];
            if (ks < cum + c) {
                g_selPrefix[blockIdx.x] = t * CH + i;
                g_selRank[blockIdx.x] = ks - cum;
                break;
            }
            cum += c;
        }
    }
}

// ------------------- 7. pass-2 histogram (low 16 bits in bucket) ------------
__global__ void pass2_kernel() {
    __shared__ int sp0[NBC], sp1[NBC];
    if (threadIdx.x < NBC) {
        sp0[threadIdx.x] = g_selPrefix[2 * threadIdx.x];
        sp1[threadIdx.x] = g_selPrefix[2 * threadIdx.x + 1];
    }
    __syncthreads();
    int i = blockIdx.x * blockDim.x + threadIdx.x;   // NBC*NP divisible by 256: full warps
    int bc = i >> 18;                                 // uniform per warp
    unsigned key = __float_as_uint(g_J[i]);
    int pre = (int)(key >> 16);
    int low = (int)(key & 0xFFFFu);
    whist_add(&g_hist2[(bc * 2) * H2BINS], low, pre == sp0[bc]);
    whist_add(&g_hist2[(bc * 2 + 1) * H2BINS], low, pre == sp1[bc]);
}

// ------------------- 8. exact k-th value from pass-2 histogram ---------------
__global__ void scan2_kernel() {
    int idx = blockIdx.x;                       // bc*2 + sel
    const unsigned* h = g_hist2 + idx * H2BINS;
    unsigned ks = g_selRank[idx];

    __shared__ unsigned part[257];
    int t = threadIdx.x;
    const int CH = H2BINS / 256;                // 256
    unsigned s = 0;
    for (int i = 0; i < CH; i++) s += h[t * CH + i];
    part[t] = s;
    __syncthreads();
    if (t == 0) {
        unsigned run = 0;
        for (int i = 0; i < 256; i++) { unsigned v = part[i]; part[i] = run; run += v; }
        part[256] = run;
    }
    __syncthreads();
    if (ks >= part[t] && ks < part[t + 1]) {
        unsigned cum = part[t];
        for (int i = 0; i < CH; i++) {
            unsigned c = h[t * CH + i];
            if (ks < cum + c) {
                unsigned bits = ((unsigned)g_selPrefix[idx] << 16) | (unsigned)(t * CH + i);
                float v = __uint_as_float(bits);
                int bc = idx >> 1;
                if (idx & 1) g_phigh[bc] = v; else g_plow[bc] = v;
                break;
            }
            cum += c;
        }
    }
}

__global__ void pscale_kernel() {
    int bc = threadIdx.x;
    if (bc < NBC) {
        g_pscale[bc] = 1.0f / (g_phigh[bc] - g_plow[bc] + 1e-8f);
    }
}

// ------------------- 9. final normalize -------------------------------------
__global__ void final_kernel(float* __restrict__ out) {
    int i = blockIdx.x * blockDim.x + threadIdx.x;
    int bc = i >> 18;
    float pl = g_plow[bc], ph = g_phigh[bc], sc = g_pscale[bc];
    float v = g_J[i];
    v = fminf(fmaxf(v, pl), ph);
    float o = (v - pl) * sc;
    out[i] = fminf(fmaxf(o, 0.f), 1.f);
}

// ---------------------------------------------------------------------------
extern "C" void kernel_launch(void* const* d_in, const int* in_sizes, int n_in,
                              void* d_out, int out_size) {
    const float* img   = (const float*)d_in[0];
    const float* omega = (const float*)d_in[1];
    const float* atm   = (const float*)d_in[2];
    const float* Llow  = (const float*)d_in[3];
    const float* Lhigh = (const float*)d_in[4];
    const int*   rp    = (n_in > 5) ? (const int*)d_in[5] : nullptr;
    float* out = (float*)d_out;

    zero_kernel<<<3456, 256>>>();
    k1_kernel<<<(Bn * NP + 255) / 256, 256>>>(img, omega, atm);
    h1_kernel<<<Bn * Hh, 64>>>(rp);
    v1_kernel<<<dim3(Ww / 128, Hh / YSEG, Bn), 128>>>(rp);
    h2_kernel<<<Bn * Hh, 64>>>(rp);
    v2_kernel<<<dim3(Ww / 128, Hh / YSEG, Bn), 128>>>(img, atm, rp);
    scan1_kernel<<<NBC * 2, 256>>>(Llow, Lhigh);
    pass2_kernel<<<(NBC * NP) / 256, 256>>>();
    scan2_kernel<<<NBC * 2, 256>>>();
    pscale_kernel<<<1, 32>>>();
    final_kernel<<<(NBC * NP) / 256, 256>>>(out);
}